// round 6
// baseline (speedup 1.0000x reference)
#include <cuda_runtime.h>

// NashCascadeNetwork: 8 layers x 524288 buckets, 8 spigots/bucket.
// Inputs (metadata order): H[NB] f32, S[NB,8,2] f32, theta[NB*8] f32, precip[1] f32
// Output (f32): [ H_new(NB) | s_q(NB*8) | network_outflow(1) ]

#define NB         4194304
#define NS         8
#define BPL        524288                 // buckets in last layer
#define BPB        64                     // buckets per block
#define NTHREADS   256                    // 4 threads per bucket
#define NGRID      (NB / BPB)             // 65536
#define FIRST_LAST ((NB - BPL) / BPB)     // 57344
#define NLASTBLK   (BPL / BPB)            // 8192
#define OUT_SQ_OFF NB
#define OUT_SCALAR (NB * (NS + 1))        // 37748736

__device__ double g_partials[NLASTBLK];

// q = theta * sqrt(2*9.8*h) * 0.5*(tanh(h)+1) * area,  h = max(0, H - height)
// 0.5*(tanh(h)+1) == sigmoid(2h) == 1/(1+exp(-2h))  -> EX2 + RCP (err ~1e-7)
__device__ __forceinline__ float spigot_q(float Hb, float sh, float sa, float th) {
    float h = fmaxf(0.0f, Hb - sh);
    float e = __expf(-2.0f * h);
    float mod;
    asm("rcp.approx.f32 %0, %1;" : "=f"(mod) : "f"(1.0f + e));
    float s;
    asm("sqrt.approx.f32 %0, %1;" : "=f"(s) : "f"(19.6f * h));
    return th * s * mod * sa;
}

__global__ __launch_bounds__(NTHREADS)
void nash_main(const float* __restrict__ H,
               const float4* __restrict__ S4,     // [NB*4] : (h0,a0,h1,a1) per quad-lane
               const float2* __restrict__ T2,     // [NB*4]
               const float* __restrict__ precip,
               float* __restrict__ Hn,            // [NB]
               float2* __restrict__ SQ2)          // [NB*4]
{
    const int tid  = threadIdx.x;
    const int quad = tid >> 2;          // local bucket 0..63
    const int ql   = tid & 3;           // 2 spigots per lane
    const int b    = blockIdx.x * BPB + quad;

    const float  Hb = H[b];
    const float4 sv = S4[b * 4 + ql];   // fully coalesced across warp
    const float2 tv = T2[b * 4 + ql];

    const float q0 = spigot_q(Hb, sv.x, sv.y, tv.x);
    const float q1 = spigot_q(Hb, sv.z, sv.w, tv.y);
    SQ2[b * 4 + ql] = make_float2(q0, q1);

    // bucket outflow: reduce over the 4 lanes of the quad
    float po = q0 + q1;
    po += __shfl_xor_sync(0xffffffffu, po, 1);
    po += __shfl_xor_sync(0xffffffffu, po, 2);

    __shared__ float s_out[BPB];
    if (ql == 0) s_out[quad] = po;
    __syncthreads();

    if (tid == 0) {
        // inflow of the block's first bucket: precip (bucket 0) or the
        // previous block's last bucket outflow (recomputed, L2-hot).
        float prev;
        if (blockIdx.x == 0) {
            prev = *precip;
        } else {
            const int bp = b - 1;
            const float  Hp = H[bp];
            const float* Sp = (const float*)S4 + (size_t)bp * 16;
            const float* Tp = (const float*)T2 + (size_t)bp * 8;
            prev = 0.0f;
            #pragma unroll
            for (int s = 0; s < NS; s++)
                prev += spigot_q(Hp, Sp[2 * s], Sp[2 * s + 1], Tp[s]);
        }
        Hn[b] = Hb + prev - po;
    } else if (ql == 0) {
        Hn[b] = Hb + s_out[quad - 1] - po;
    }

    // last-layer partial sum (network outflow), in double for exactness
    if (blockIdx.x >= FIRST_LAST && tid == 32) {
        double a = 0.0;
        #pragma unroll 8
        for (int i = 0; i < BPB; i++) a += (double)s_out[i];
        g_partials[blockIdx.x - FIRST_LAST] = a;
    }
}

__global__ void nash_finalize(float* __restrict__ out) {
    __shared__ double sm[256];
    double a = 0.0;
    for (int i = threadIdx.x; i < NLASTBLK; i += 256) a += g_partials[i];
    sm[threadIdx.x] = a;
    __syncthreads();
    for (int s = 128; s > 0; s >>= 1) {
        if (threadIdx.x < s) sm[threadIdx.x] += sm[threadIdx.x + s];
        __syncthreads();
    }
    if (threadIdx.x == 0) out[OUT_SCALAR] = (float)sm[0];
}

extern "C" void kernel_launch(void* const* d_in, const int* in_sizes, int n_in,
                              void* d_out, int out_size) {
    const float*  H      = (const float*)d_in[0];
    const float4* S4     = (const float4*)d_in[1];
    const float2* T2     = (const float2*)d_in[2];
    const float*  precip = (const float*)d_in[3];

    float*  out = (float*)d_out;
    float*  Hn  = out;
    float2* SQ2 = (float2*)(out + OUT_SQ_OFF);

    nash_main<<<NGRID, NTHREADS>>>(H, S4, T2, precip, Hn, SQ2);
    nash_finalize<<<1, 256>>>(out);
}

// round 7
// speedup vs baseline: 1.7400x; 1.7400x over previous
#include <cuda_runtime.h>

// NashCascadeNetwork: 8 layers x 524288 buckets, 8 spigots/bucket.
// Inputs (metadata order): H[NB] f32, S[NB,8,2] f32, theta[NB*8] f32, precip[1] f32
// Output (f32): [ H_new(NB) | s_q(NB*8) | network_outflow(1) ]

#define NB         4194304
#define NS         8
#define BPL        524288                  // buckets in last layer
#define BPB        128                     // buckets per block (2 per quad)
#define NTHREADS   256
#define NGRID      (NB / BPB)              // 32768
#define FIRST_LAST ((NB - BPL) / BPB)      // 28672
#define NLASTBLK   (BPL / BPB)             // 4096
#define OUT_SQ_OFF NB
#define OUT_SCALAR (NB * (NS + 1))         // 37748736

__device__ double   g_partials[NLASTBLK];
__device__ unsigned g_count = 0;

// q = theta * sqrt(2*9.8*h) * 0.5*(tanh(h)+1) * area,  h = max(0, H - height)
// 0.5*(tanh(h)+1) == sigmoid(2h) == 1/(1+exp(-2h))  -> EX2 + RCP (err ~1e-7)
__device__ __forceinline__ float spigot_q(float Hb, float sh, float sa, float th) {
    float h = fmaxf(0.0f, Hb - sh);
    float e = __expf(-2.0f * h);
    float mod;
    asm("rcp.approx.f32 %0, %1;" : "=f"(mod) : "f"(1.0f + e));
    float s;
    asm("sqrt.approx.f32 %0, %1;" : "=f"(s) : "f"(19.6f * h));
    return th * s * mod * sa;
}

__global__ __launch_bounds__(NTHREADS)
void nash_main(const float* __restrict__ H,
               const float4* __restrict__ S4,     // [NB*4] : (h0,a0,h1,a1) per quad-lane
               const float2* __restrict__ T2,     // [NB*4]
               const float* __restrict__ precip,
               float* __restrict__ out)           // full output buffer
{
    float*  Hn  = out;
    float2* SQ2 = (float2*)(out + OUT_SQ_OFF);

    const int tid  = threadIdx.x;
    const int quad = tid >> 2;              // 0..63
    const int ql   = tid & 3;               // 2 spigots per lane
    const int b0   = blockIdx.x * BPB;
    const int bA   = b0 + quad;
    const int bB   = bA + 64;

    // ---- front-batched streaming loads (2 buckets per quad) ----
    const float  HA = H[bA];
    const float  HB = H[bB];
    const float4 sA = __ldcs(&S4[(size_t)bA * 4 + ql]);
    const float4 sB = __ldcs(&S4[(size_t)bB * 4 + ql]);
    const float2 tA = __ldcs(&T2[(size_t)bA * 4 + ql]);
    const float2 tB = __ldcs(&T2[(size_t)bB * 4 + ql]);

    // Boundary bucket (b0-1) handled in parallel by lanes 0..3 of warp 0.
    float pe = 0.0f;
    if (tid < 4 && blockIdx.x != 0) {
        const int    bp = b0 - 1;
        const float  Hp = H[bp];
        const float4 sp = S4[(size_t)bp * 4 + tid];
        const float2 tp = T2[(size_t)bp * 4 + tid];
        pe = spigot_q(Hp, sp.x, sp.y, tp.x) + spigot_q(Hp, sp.z, sp.w, tp.y);
    }

    const float qA0 = spigot_q(HA, sA.x, sA.y, tA.x);
    const float qA1 = spigot_q(HA, sA.z, sA.w, tA.y);
    const float qB0 = spigot_q(HB, sB.x, sB.y, tB.x);
    const float qB1 = spigot_q(HB, sB.z, sB.w, tB.y);

    __stcs(&SQ2[(size_t)bA * 4 + ql], make_float2(qA0, qA1));
    __stcs(&SQ2[(size_t)bB * 4 + ql], make_float2(qB0, qB1));

    // ---- bucket outflows: reduce over the 4 lanes of each quad ----
    float poA = qA0 + qA1;
    float poB = qB0 + qB1;
    poA += __shfl_xor_sync(0xffffffffu, poA, 1);
    poA += __shfl_xor_sync(0xffffffffu, poA, 2);
    poB += __shfl_xor_sync(0xffffffffu, poB, 1);
    poB += __shfl_xor_sync(0xffffffffu, poB, 2);

    __shared__ float s_out[BPB];
    __shared__ bool  s_last;
    if (tid == 0) s_last = false;
    if (ql == 0) { s_out[quad] = poA; s_out[quad + 64] = poB; }

    if (tid < 32) {                          // warp 0 only: finish boundary sum
        pe += __shfl_xor_sync(0xffffffffu, pe, 1);
        pe += __shfl_xor_sync(0xffffffffu, pe, 2);
    }
    __syncthreads();

    // ---- H_new[b] = H[b] + outflow[b-1] - outflow[b] ----
    if (ql == 0) {
        float prevA = (quad == 0)
                    ? ((blockIdx.x == 0) ? __ldg(precip) : pe)
                    : s_out[quad - 1];
        __stcs(&Hn[bA], HA + prevA - poA);
        __stcs(&Hn[bB], HB + s_out[quad + 63] - poB);
    }

    // ---- last-layer network-outflow reduction (fused, deterministic) ----
    if (blockIdx.x >= FIRST_LAST) {
        if (tid < 32) {
            double a = (double)s_out[tid]      + (double)s_out[tid + 32]
                     + (double)s_out[tid + 64] + (double)s_out[tid + 96];
            a += __shfl_xor_sync(0xffffffffu, a, 16);
            a += __shfl_xor_sync(0xffffffffu, a, 8);
            a += __shfl_xor_sync(0xffffffffu, a, 4);
            a += __shfl_xor_sync(0xffffffffu, a, 2);
            a += __shfl_xor_sync(0xffffffffu, a, 1);
            if (tid == 0) {
                g_partials[blockIdx.x - FIRST_LAST] = a;
                __threadfence();
                unsigned t = atomicAdd(&g_count, 1u);
                if (t == NLASTBLK - 1) s_last = true;
            }
        }
        __syncthreads();
        if (s_last) {
            // Last block alive: fixed-order reduction of all partials
            // (order depends only on tid -> bit-deterministic).
            __threadfence();
            double a = 0.0;
            #pragma unroll 4
            for (int i = tid; i < NLASTBLK; i += NTHREADS)
                a += g_partials[i];
            __shared__ double sm[NTHREADS];
            sm[tid] = a;
            __syncthreads();
            #pragma unroll
            for (int s = NTHREADS / 2; s > 0; s >>= 1) {
                if (tid < s) sm[tid] += sm[tid + s];
                __syncthreads();
            }
            if (tid == 0) {
                out[OUT_SCALAR] = (float)sm[0];
                g_count = 0;                 // reset for graph replay
            }
        }
    }
}

extern "C" void kernel_launch(void* const* d_in, const int* in_sizes, int n_in,
                              void* d_out, int out_size) {
    const float*  H      = (const float*)d_in[0];
    const float4* S4     = (const float4*)d_in[1];
    const float2* T2     = (const float2*)d_in[2];
    const float*  precip = (const float*)d_in[3];

    nash_main<<<NGRID, NTHREADS>>>(H, S4, T2, precip, (float*)d_out);
}